// round 16
// baseline (speedup 1.0000x reference)
#include <cuda_runtime.h>
#include <cuda_fp16.h>
#include <math.h>
#include <stdint.h>

// Problem constants
#define BB   4
#define SS   2048
#define DM   512
#define DF   2048
#define ROWS (BB*SS)   // 8192

// GEMM constants
#define BN  128
#define BKH 64                  // K per tile, in halves (128 B rows)
#define RP  72                  // padded row pitch in halves (144 B)
#define NSTAGE 3
#define SMEM_T(TBM) (NSTAGE*((TBM)+BN)*RP*2)
#define SMEM_128 SMEM_T(128)    // 110592 B -> 2 CTAs/SM
#define SMEM_64  SMEM_T(64)     // 82944 B  -> 2 CTAs/SM

// prep kernel block ranges
#define PREP_F2H (ROWS*DM/1024)          // 4096 blocks per tensor
#define PREP_R0  (PREP_F2H*3)            // 12288: end of f2h region
#define PREP_R1  (PREP_R0 + 768)         // sq transposes (16*16*3)
#define PREP_R2  (PREP_R1 + 1024)        // W1 transpose (16*64)
#define PREP_TOT (PREP_R2 + 1024)        // W2 transpose (64*16)

// ---------------- scratch (device globals; no runtime alloc allowed) ----------------
__device__ __half g_qh[ROWS*DM];
__device__ __half g_kh[ROWS*DM];
__device__ __half g_vh[ROWS*DM];
__device__ __half g_Qh[ROWS*DM];
__device__ __half g_Kh[ROWS*DM];
__device__ __half g_VTh[ROWS*DM];             // V^T per batch [B][D][S] (written by QKV epilogue)
__device__ __half g_Ph[(size_t)BB*SS*SS];     // half unnormalized exp(scores) (32 MB)
__device__ float  g_rinv[ROWS];               // per-row 1/sum(exp)
__device__ float  g_attn[ROWS*DM];
__device__ float  g_h[ROWS*DM];
__device__ __half g_hh[ROWS*DM];
__device__ __half g_f[ROWS*DF];               // FFN hidden, half
__device__ float  g_f2[ROWS*DM];
__device__ __half g_WqT[DM*DM];
__device__ __half g_WkT[DM*DM];
__device__ __half g_WvT[DM*DM];
__device__ __half g_W1T[(size_t)DF*DM];
__device__ __half g_W2T[(size_t)DM*DF];

// ---------------- helpers ----------------
__device__ __forceinline__ uint32_t smem_u32(const void* p) {
    return (uint32_t)__cvta_generic_to_shared(p);
}
__device__ __forceinline__ void cp_async16(void* dst, const void* src) {
    asm volatile("cp.async.cg.shared.global [%0], [%1], 16;"
                 :: "r"(smem_u32(dst)), "l"(src));
}
__device__ __forceinline__ void cp_commit() {
    asm volatile("cp.async.commit_group;");
}
__device__ __forceinline__ void cp_wait1() {
    asm volatile("cp.async.wait_group 1;");
}

__device__ __forceinline__ void ldsm_x4(uint32_t& r0, uint32_t& r1,
                                        uint32_t& r2, uint32_t& r3, uint32_t addr) {
    asm volatile("ldmatrix.sync.aligned.m8n8.x4.shared.b16 {%0,%1,%2,%3}, [%4];"
                 : "=r"(r0), "=r"(r1), "=r"(r2), "=r"(r3) : "r"(addr));
}

__device__ __forceinline__ void mma_f16(float c[4],
                                        uint32_t a0, uint32_t a1, uint32_t a2, uint32_t a3,
                                        uint32_t b0, uint32_t b1) {
    asm volatile(
        "mma.sync.aligned.m16n8k16.row.col.f32.f16.f16.f32 "
        "{%0,%1,%2,%3}, {%4,%5,%6,%7}, {%8,%9}, {%0,%1,%2,%3};"
        : "+f"(c[0]), "+f"(c[1]), "+f"(c[2]), "+f"(c[3])
        : "r"(a0), "r"(a1), "r"(a2), "r"(a3), "r"(b0), "r"(b1));
}

// ---------------- fp16 GEMM core (templated M-tile) ----------------
// C = alpha*(A[M,K] @ Bt[N,K]^T + bias), optional relu / exp / half-out / transposed-out.
// TBM in {128, 64}. CTA tile TBM x 128, 256 threads, warp tile (TBM/2) x 32.
// TBM=128 instantiation is index-identical to the R6-proven kernel.
template<int TBM, int HASBIAS, int RELU, int OUTH, int EXPF, int VT>
__device__ __forceinline__ void gemm_core(
    const __half* __restrict__ Ab, const __half* __restrict__ Bb,
    const float* __restrict__ bias, void* __restrict__ Cvb,
    int m0, int n0, int N, int K, float alpha)
{
    constexpr int MT   = TBM / 32;          // 4 or 2 m-subtiles per warp
    constexpr int WMO  = TBM / 2;           // warp M offset
    constexpr int ASTG = TBM * RP;
    constexpr int STG  = (TBM + BN) * RP;
    constexpr int ACH  = TBM * 8 / 256;     // A cp.async chunks per thread

    extern __shared__ __half hsm[];

    const int tid = threadIdx.x;
    const int wid = tid >> 5, lane = tid & 31;
    const int g   = lane >> 2, t4 = lane & 3;
    const int wm  = wid >> 2, wn = wid & 3;        // 2 x 4 warp grid

    const int arow = lane & 15;
    const int acol = (lane >> 4) << 3;
    const int brow = (lane & 7) + ((lane >> 4) << 3);
    const int bcol = ((lane >> 3) & 1) << 3;

    float c[MT][4][4] = {};

    auto aBase = [&](int s) { return hsm + s * STG; };
    auto bBase = [&](int s) { return hsm + s * STG + ASTG; };

    auto loadA = [&](int s, int k0) {
        __half* base = aBase(s);
        #pragma unroll
        for (int i = 0; i < ACH; i++) {
            int ch = tid + i * 256;
            int r = ch >> 3, cc = ch & 7;
            cp_async16(base + r * RP + cc * 8,
                       Ab + (size_t)(m0 + r) * K + k0 + cc * 8);
        }
    };
    auto loadB = [&](int s, int k0) {
        __half* base = bBase(s);
        #pragma unroll
        for (int i = 0; i < 4; i++) {
            int ch = tid + i * 256;
            int r = ch >> 3, cc = ch & 7;
            cp_async16(base + r * RP + cc * 8,
                       Bb + (size_t)(n0 + r) * K + k0 + cc * 8);
        }
    };

    const int T = K / BKH;

    loadA(0, 0);   loadB(0, 0);   cp_commit();
    loadA(1, BKH); loadB(1, BKH); cp_commit();

    for (int t = 0; t < T; t++) {
        cp_wait1();
        __syncthreads();
        int tn = t + 2;
        if (tn < T) { loadA(tn % NSTAGE, tn * BKH); loadB(tn % NSTAGE, tn * BKH); }
        cp_commit();

        const int p = t % NSTAGE;
        const uint32_t As0 = smem_u32(aBase(p));
        const uint32_t Bs0 = smem_u32(bBase(p));

        #pragma unroll
        for (int ks = 0; ks < 4; ks++) {
            const int kh = ks * 16;
            uint32_t a[MT][4], b[4][2];
            #pragma unroll
            for (int mt = 0; mt < MT; mt++) {
                uint32_t addr = As0 + ((wm * WMO + mt * 16 + arow) * RP + kh + acol) * 2;
                ldsm_x4(a[mt][0], a[mt][1], a[mt][2], a[mt][3], addr);
            }
            #pragma unroll
            for (int np = 0; np < 2; np++) {
                uint32_t addr = Bs0 + ((wn * 32 + np * 16 + brow) * RP + kh + bcol) * 2;
                ldsm_x4(b[2*np][0], b[2*np][1], b[2*np+1][0], b[2*np+1][1], addr);
            }
            #pragma unroll
            for (int mt = 0; mt < MT; mt++)
                #pragma unroll
                for (int nt = 0; nt < 4; nt++)
                    mma_f16(c[mt][nt], a[mt][0], a[mt][1], a[mt][2], a[mt][3],
                            b[nt][0], b[nt][1]);
        }
    }

    // epilogue
    #pragma unroll
    for (int mt = 0; mt < MT; mt++) {
        #pragma unroll
        for (int nt = 0; nt < 4; nt++) {
            const int col = n0 + wn * 32 + nt * 8 + 2 * t4;
            float b0 = 0.f, b1 = 0.f;
            if (HASBIAS) { b0 = bias[col]; b1 = bias[col + 1]; }
            #pragma unroll
            for (int h = 0; h < 2; h++) {
                const int row = m0 + wm * WMO + mt * 16 + g + h * 8;
                float v0 = (c[mt][nt][2 * h + 0] + b0) * alpha;
                float v1 = (c[mt][nt][2 * h + 1] + b1) * alpha;
                if (RELU) { v0 = fmaxf(v0, 0.f); v1 = fmaxf(v1, 0.f); }
                if (EXPF) { v0 = __expf(v0);     v1 = __expf(v1); }
                if (VT) {
                    // transposed half store: [b][col][s]
                    __half* Cb = (__half*)Cvb;
                    const int bb2 = row >> 11;            // row / SS
                    const int s  = row & (SS - 1);
                    Cb[((size_t)bb2 * DM + col)     * SS + s] = __float2half_rn(v0);
                    Cb[((size_t)bb2 * DM + col + 1) * SS + s] = __float2half_rn(v1);
                } else if (OUTH) {
                    __half* Cb = (__half*)Cvb;
                    *(__half2*)&Cb[(size_t)row * N + col] = __floats2half2_rn(v0, v1);
                } else {
                    float* Cb = (float*)Cvb;
                    *(float2*)&Cb[(size_t)row * N + col] = make_float2(v0, v1);
                }
            }
        }
    }
}

// generic batched-by-stride GEMM (128-tile)
template<int HASBIAS, int RELU, int OUTH, int EXPF>
__global__ void __launch_bounds__(256, 2)
gemm_h(const __half* __restrict__ A, const __half* __restrict__ Bt,
       const float* __restrict__ bias, void* __restrict__ Cv,
       int N, int K, size_t sA, size_t sB, size_t sC, float alpha)
{
    const __half* Ab = A  + (size_t)blockIdx.z * sA;
    const __half* Bb = Bt + (size_t)blockIdx.z * sB;
    void* Cb = OUTH ? (void*)((__half*)Cv + (size_t)blockIdx.z * sC)
                    : (void*)((float*)Cv + (size_t)blockIdx.z * sC);
    gemm_core<128, HASBIAS, RELU, OUTH, EXPF, 0>(Ab, Bb, bias, Cb,
                                                 blockIdx.y * 128, blockIdx.x * BN,
                                                 N, K, alpha);
}

// fused QKV: one launch, blockIdx.z selects q/k/v; V (z==2) is written transposed.
__global__ void __launch_bounds__(256, 2)
gemm_qkv(const __half* __restrict__ qa, const __half* __restrict__ ka,
         const __half* __restrict__ va,
         const __half* __restrict__ wq, const __half* __restrict__ wk,
         const __half* __restrict__ wv,
         const float* __restrict__ bq, const float* __restrict__ bk,
         const float* __restrict__ bv,
         __half* __restrict__ oq, __half* __restrict__ ok,
         __half* __restrict__ ovt, float alphaQ)
{
    const int z = blockIdx.z;
    const int m0 = blockIdx.y * 128, n0 = blockIdx.x * BN;
    if (z == 2) {
        gemm_core<128, 1, 0, 1, 0, 1>(va, wv, bv, ovt, m0, n0, DM, DM, 1.f);
    } else {
        const __half* Ab = (z == 0) ? qa : ka;
        const __half* Bb = (z == 0) ? wq : wk;
        const float*  bb = (z == 0) ? bq : bk;
        __half*       Cb = (z == 0) ? oq : ok;
        const float   al = (z == 0) ? alphaQ : 1.f;
        gemm_core<128, 1, 0, 1, 0, 0>(Ab, Bb, bb, Cb, m0, n0, DM, DM, al);
    }
}

// fused P@V (64x128 tiles) + rowsum: grid (4, SS/64 + 1, BB) = (4, 33, 4) = 528 CTAs.
// blockIdx.y < 32 : GEMM CTA (attn_unnorm = P @ V), M-tile 64
// blockIdx.y == 32: rowsum CTA — 16 such CTAs, each sums 512 rows of P
__global__ void __launch_bounds__(256, 2)
gemm_pv_rowsum(const __half* __restrict__ P, const __half* __restrict__ VT,
               float* __restrict__ attn, float* __restrict__ rinv)
{
    if (blockIdx.y == SS / 64) {
        const int warp = threadIdx.x >> 5, lane = threadIdx.x & 31;
        const int chunk = blockIdx.z * 4 + blockIdx.x;           // 0..15
        #pragma unroll 1
        for (int i = 0; i < 64; i++) {
            const size_t row = (size_t)chunk * 512 + warp * 64 + i;
            const uint4* p = (const uint4*)(P + row * SS);       // 256 uint4
            float s = 0.f;
            #pragma unroll
            for (int j = 0; j < 8; j++) {
                uint4 u = p[lane + j * 32];
                const __half2* h = (const __half2*)&u;
                #pragma unroll
                for (int t = 0; t < 4; t++) {
                    float2 f = __half22float2(h[t]);
                    s += f.x + f.y;
                }
            }
            #pragma unroll
            for (int o = 16; o; o >>= 1) s += __shfl_xor_sync(0xffffffffu, s, o);
            if (lane == 0) rinv[row] = 1.f / s;
        }
        return;
    }
    const __half* Ab = P  + (size_t)blockIdx.z * SS * SS;
    const __half* Bb = VT + (size_t)blockIdx.z * DM * SS;
    float*        Cb = attn + (size_t)blockIdx.z * SS * DM;
    gemm_core<64, 0, 0, 0, 0, 0>(Ab, Bb, nullptr, Cb,
                                 blockIdx.y * 64, blockIdx.x * BN, DM, SS, 1.f);
}

// ---------------- ONE prep launch: f2h of q/k/v + all 5 weight transposes ----------------
__global__ void prep_kernel(
    const float* __restrict__ q, const float* __restrict__ k, const float* __restrict__ v,
    __half* __restrict__ oq, __half* __restrict__ ok, __half* __restrict__ ov,
    const float* __restrict__ Wq, const float* __restrict__ Wk, const float* __restrict__ Wv,
    __half* __restrict__ oWq, __half* __restrict__ oWk, __half* __restrict__ oWv,
    const float* __restrict__ W1, __half* __restrict__ oW1,
    const float* __restrict__ W2, __half* __restrict__ oW2)
{
    const int b = blockIdx.x;

    if (b < PREP_R0) {
        const int t  = b / PREP_F2H;
        const int bx = b % PREP_F2H;
        const float* in  = (t == 0) ? q  : (t == 1) ? k  : v;
        __half*      out = (t == 0) ? oq : (t == 1) ? ok : ov;
        const int i = (bx * 256 + threadIdx.x) * 4;
        float4 val = *(const float4*)(in + i);
        *(__half2*)(out + i)     = __floats2half2_rn(val.x, val.y);
        *(__half2*)(out + i + 2) = __floats2half2_rn(val.z, val.w);
        return;
    }

    __shared__ float tile[32][33];
    const int tx = threadIdx.x & 31, ty = threadIdx.x >> 5;
    const float* in; __half* out; int R, C, r0, c0;

    if (b < PREP_R1) {
        const int local = b - PREP_R0;
        const int z = local / 256, rem = local % 256;
        in  = (z == 0) ? Wq  : (z == 1) ? Wk  : Wv;
        out = (z == 0) ? oWq : (z == 1) ? oWk : oWv;
        R = DM; C = DM;
        r0 = (rem & 15) * 32;
        c0 = (rem >> 4) * 32;
    } else if (b < PREP_R2) {
        const int local = b - PREP_R1;
        in = W1; out = oW1; R = DM; C = DF;
        r0 = (local & 15) * 32;
        c0 = (local >> 4) * 32;
    } else {
        const int local = b - PREP_R2;
        in = W2; out = oW2; R = DF; C = DM;
        r0 = (local & 63) * 32;
        c0 = (local >> 6) * 32;
    }

    #pragma unroll
    for (int i = 0; i < 4; i++)
        tile[ty + i * 8][tx] = in[(size_t)(r0 + ty + i * 8) * C + c0 + tx];
    __syncthreads();
    #pragma unroll
    for (int i = 0; i < 4; i++)
        out[(size_t)(c0 + ty + i * 8) * R + r0 + tx] = __float2half_rn(tile[tx][ty + i * 8]);
}

// ---------------- warp-per-row residual add + LayerNorm (no block barriers) ----------------
template<int WRITEH, int SCALEA>
__global__ void add_ln_warp(const float* __restrict__ a, const float* __restrict__ b,
                            const float* __restrict__ gamma, const float* __restrict__ beta,
                            const float* __restrict__ ascale,
                            float* __restrict__ out, __half* __restrict__ outh)
{
    const int warp = threadIdx.x >> 5, lane = threadIdx.x & 31;
    const size_t row = (size_t)blockIdx.x * 8 + warp;
    const float4* ar = (const float4*)(a + row * DM);
    const float4* br = (const float4*)(b + row * DM);

    const float sc = SCALEA ? ascale[row] : 1.f;

    float4 v[4];
    float s = 0.f, sq = 0.f;
    #pragma unroll
    for (int i = 0; i < 4; i++) {
        float4 av = ar[lane + 32 * i];
        float4 bv = br[lane + 32 * i];
        v[i].x = av.x * sc + bv.x;
        v[i].y = av.y * sc + bv.y;
        v[i].z = av.z * sc + bv.z;
        v[i].w = av.w * sc + bv.w;
        s  += v[i].x + v[i].y + v[i].z + v[i].w;
        sq += v[i].x*v[i].x + v[i].y*v[i].y + v[i].z*v[i].z + v[i].w*v[i].w;
    }
    #pragma unroll
    for (int o = 16; o; o >>= 1) {
        s  += __shfl_xor_sync(0xffffffffu, s,  o);
        sq += __shfl_xor_sync(0xffffffffu, sq, o);
    }

    const float mean = s * (1.f / DM);
    const float var  = sq * (1.f / DM) - mean * mean;
    const float inv  = rsqrtf(var + 1e-5f);

    float4* o4 = (float4*)(out + row * DM);
    #pragma unroll
    for (int i = 0; i < 4; i++) {
        const int idx = lane + 32 * i;
        float4 gv = ((const float4*)gamma)[idx];
        float4 be = ((const float4*)beta)[idx];
        float4 o;
        o.x = (v[i].x - mean) * inv * gv.x + be.x;
        o.y = (v[i].y - mean) * inv * gv.y + be.y;
        o.z = (v[i].z - mean) * inv * gv.z + be.z;
        o.w = (v[i].w - mean) * inv * gv.w + be.w;
        o4[idx] = o;
        if (WRITEH) {
            __half2* oh = (__half2*)(outh + row * DM) + idx * 2;
            oh[0] = __floats2half2_rn(o.x, o.y);
            oh[1] = __floats2half2_rn(o.z, o.w);
        }
    }
}

// ---------------- launch ----------------
extern "C" void kernel_launch(void* const* d_in, const int* in_sizes, int n_in,
                              void* d_out, int out_size)
{
    const float* q  = (const float*)d_in[0];
    const float* k  = (const float*)d_in[1];
    const float* v  = (const float*)d_in[2];
    const float* x  = (const float*)d_in[3];
    const float* Wq = (const float*)d_in[4];
    const float* bq = (const float*)d_in[5];
    const float* Wk = (const float*)d_in[6];
    const float* bk = (const float*)d_in[7];
    const float* Wv = (const float*)d_in[8];
    const float* bv = (const float*)d_in[9];
    const float* g1 = (const float*)d_in[10];
    const float* be1= (const float*)d_in[11];
    const float* W1 = (const float*)d_in[12];
    const float* b1 = (const float*)d_in[13];
    const float* W2 = (const float*)d_in[14];
    const float* b2 = (const float*)d_in[15];
    const float* g2 = (const float*)d_in[16];
    const float* be2= (const float*)d_in[17];
    float* out = (float*)d_out;

    __half *pqh, *pkh, *pvh, *pQh, *pKh, *pVTh, *pPh, *phh, *pf;
    __half *pWqT, *pWkT, *pWvT, *pW1T, *pW2T;
    float *pRinv, *pAttn, *pH, *pF2;
    cudaGetSymbolAddress((void**)&pqh,  g_qh);
    cudaGetSymbolAddress((void**)&pkh,  g_kh);
    cudaGetSymbolAddress((void**)&pvh,  g_vh);
    cudaGetSymbolAddress((void**)&pQh,  g_Qh);
    cudaGetSymbolAddress((void**)&pKh,  g_Kh);
    cudaGetSymbolAddress((void**)&pVTh, g_VTh);
    cudaGetSymbolAddress((void**)&pPh,  g_Ph);
    cudaGetSymbolAddress((void**)&pRinv,g_rinv);
    cudaGetSymbolAddress((void**)&pAttn,g_attn);
    cudaGetSymbolAddress((void**)&pH,   g_h);
    cudaGetSymbolAddress((void**)&phh,  g_hh);
    cudaGetSymbolAddress((void**)&pf,   g_f);
    cudaGetSymbolAddress((void**)&pF2,  g_f2);
    cudaGetSymbolAddress((void**)&pWqT, g_WqT);
    cudaGetSymbolAddress((void**)&pWkT, g_WkT);
    cudaGetSymbolAddress((void**)&pWvT, g_WvT);
    cudaGetSymbolAddress((void**)&pW1T, g_W1T);
    cudaGetSymbolAddress((void**)&pW2T, g_W2T);

    cudaFuncSetAttribute((const void*)gemm_qkv,        cudaFuncAttributeMaxDynamicSharedMemorySize, SMEM_128);
    cudaFuncSetAttribute((const void*)gemm_pv_rowsum,  cudaFuncAttributeMaxDynamicSharedMemorySize, SMEM_64);
    cudaFuncSetAttribute((const void*)gemm_h<0,0,1,1>, cudaFuncAttributeMaxDynamicSharedMemorySize, SMEM_128);
    cudaFuncSetAttribute((const void*)gemm_h<1,1,1,0>, cudaFuncAttributeMaxDynamicSharedMemorySize, SMEM_128);
    cudaFuncSetAttribute((const void*)gemm_h<1,0,0,0>, cudaFuncAttributeMaxDynamicSharedMemorySize, SMEM_128);

    const float inv_sqrt_d = 1.f / sqrtf((float)DM);

    // 0) ALL prep in one launch: q/k/v fp32->fp16 + 5 weight transposes
    prep_kernel<<<PREP_TOT, 256>>>(q, k, v, pqh, pkh, pvh,
                                   Wq, Wk, Wv, pWqT, pWkT, pWvT,
                                   W1, pW1T, W2, pW2T);

    // 1) QKV projections, single fused launch; V written directly transposed
    {
        dim3 grid(DM / BN, ROWS / 128, 3);
        gemm_qkv<<<grid, 256, SMEM_128>>>(pqh, pkh, pvh, pWqT, pWkT, pWvT,
                                          bq, bk, bv, pQh, pKh, pVTh, inv_sqrt_d);
    }

    // 2) P = exp(Qs @ K^T) -> half, fused epilogue (no max-sub: |scores| <~ 6)
    {
        dim3 grid(SS / BN, SS / 128, BB);
        gemm_h<0,0,1,1><<<grid, 256, SMEM_128>>>(pQh, pKh, nullptr, pPh, SS, DM,
                                                 (size_t)SS*DM, (size_t)SS*DM, (size_t)SS*SS, 1.f);
    }

    // 3) attn_unnorm = P @ V (64x128 tiles, 512 GEMM CTAs) + rowsum, ONE launch
    {
        dim3 grid(DM / BN, SS / 64 + 1, BB);
        gemm_pv_rowsum<<<grid, 256, SMEM_64>>>(pPh, pVTh, pAttn, pRinv);
    }

    // 4) h = LN(attn_unnorm * rinv + x), warp-per-row, fp32 + half copy
    add_ln_warp<1,1><<<ROWS / 8, 256>>>(pAttn, x, g1, be1, pRinv, pH, phh);

    // 5) f = relu(h @ W1 + b1) -> half
    {
        dim3 grid(DF / BN, ROWS / 128, 1);
        gemm_h<1,1,1,0><<<grid, 256, SMEM_128>>>(phh, pW1T, b1, pf, DF, DM, 0, 0, 0, 1.f);
    }

    // 6) f2 = f @ W2 + b2 -> fp32
    {
        dim3 grid(DM / BN, ROWS / 128, 1);
        gemm_h<1,0,0,0><<<grid, 256, SMEM_128>>>(pf, pW2T, b2, pF2, DM, DF, 0, 0, 0, 1.f);
    }

    // 7) out = LN(f2 + h), warp-per-row
    add_ln_warp<0,0><<<ROWS / 8, 256>>>(pF2, pH, g2, be2, nullptr, out, nullptr);
}

// round 17
// speedup vs baseline: 1.0745x; 1.0745x over previous
#include <cuda_runtime.h>
#include <cuda_fp16.h>
#include <math.h>
#include <stdint.h>

// Problem constants
#define BB   4
#define SS   2048
#define DM   512
#define DF   2048
#define ROWS (BB*SS)   // 8192

// GEMM constants (R6-proven config)
#define BM  128
#define BN  128
#define BKH 64                  // K per tile, in halves (128 B rows)
#define RP  72                  // padded row pitch in halves (144 B)
#define ASTG_H (BM*RP)
#define STG_H (2*ASTG_H)
#define NSTAGE 3
#define SMEM_H (NSTAGE*STG_H*2) // 110592 B -> 2 CTAs/SM

// prep kernel block ranges
#define PREP_F2H (ROWS*DM/1024)          // 4096 blocks per tensor
#define PREP_R0  (PREP_F2H*3)            // 12288: end of f2h region
#define PREP_R1  (PREP_R0 + 768)         // sq transposes (16*16*3)
#define PREP_R2  (PREP_R1 + 1024)        // W1 transpose (16*64)
#define PREP_TOT (PREP_R2 + 1024)        // W2 transpose (64*16)

// ---------------- scratch (device globals; no runtime alloc allowed) ----------------
__device__ __half g_qh[ROWS*DM];
__device__ __half g_kh[ROWS*DM];
__device__ __half g_vh[ROWS*DM];
__device__ __half g_Qh[ROWS*DM];
__device__ __half g_Kh[ROWS*DM];
__device__ __half g_VTh[ROWS*DM];             // V^T per batch [B][D][S] (written by QKV epilogue)
__device__ __half g_Ph[(size_t)BB*SS*SS];     // half unnormalized exp(scores) (32 MB)
__device__ float  g_rinv[ROWS];               // per-row 1/sum(exp)
__device__ float  g_attn[ROWS*DM];
__device__ float  g_h[ROWS*DM];
__device__ __half g_hh[ROWS*DM];
__device__ __half g_f[ROWS*DF];               // FFN hidden, half
__device__ float  g_f2[ROWS*DM];
__device__ __half g_WqT[DM*DM];
__device__ __half g_WkT[DM*DM];
__device__ __half g_WvT[DM*DM];
__device__ __half g_W1T[(size_t)DF*DM];
__device__ __half g_W2T[(size_t)DM*DF];

// ---------------- helpers ----------------
__device__ __forceinline__ uint32_t smem_u32(const void* p) {
    return (uint32_t)__cvta_generic_to_shared(p);
}
__device__ __forceinline__ void cp_async16(void* dst, const void* src) {
    asm volatile("cp.async.cg.shared.global [%0], [%1], 16;"
                 :: "r"(smem_u32(dst)), "l"(src));
}
__device__ __forceinline__ void cp_commit() {
    asm volatile("cp.async.commit_group;");
}
__device__ __forceinline__ void cp_wait1() {
    asm volatile("cp.async.wait_group 1;");
}

__device__ __forceinline__ void ldsm_x4(uint32_t& r0, uint32_t& r1,
                                        uint32_t& r2, uint32_t& r3, uint32_t addr) {
    asm volatile("ldmatrix.sync.aligned.m8n8.x4.shared.b16 {%0,%1,%2,%3}, [%4];"
                 : "=r"(r0), "=r"(r1), "=r"(r2), "=r"(r3) : "r"(addr));
}

__device__ __forceinline__ void mma_f16(float c[4],
                                        uint32_t a0, uint32_t a1, uint32_t a2, uint32_t a3,
                                        uint32_t b0, uint32_t b1) {
    asm volatile(
        "mma.sync.aligned.m16n8k16.row.col.f32.f16.f16.f32 "
        "{%0,%1,%2,%3}, {%4,%5,%6,%7}, {%8,%9}, {%0,%1,%2,%3};"
        : "+f"(c[0]), "+f"(c[1]), "+f"(c[2]), "+f"(c[3])
        : "r"(a0), "r"(a1), "r"(a2), "r"(a3), "r"(b0), "r"(b1));
}

// ---------------- fp16 GEMM core (R6 config, resolved pointers) ----------------
// C = alpha*(A[M,K] @ Bt[N,K]^T + bias), optional relu / exp / half-out / transposed-out.
// VT=1: write half output transposed per batch: C[b][col][s], b=row/SS, s=row%SS.
template<int HASBIAS, int RELU, int OUTH, int EXPF, int VT>
__device__ __forceinline__ void gemm_core(
    const __half* __restrict__ Ab, const __half* __restrict__ Bb,
    const float* __restrict__ bias, void* __restrict__ Cvb,
    int N, int K, float alpha)
{
    extern __shared__ __half hsm[];

    const int tid = threadIdx.x;
    const int wid = tid >> 5, lane = tid & 31;
    const int g   = lane >> 2, t4 = lane & 3;
    const int wm  = wid >> 2, wn = wid & 3;        // 2 x 4 warp grid
    const int m0  = blockIdx.y * BM;
    const int n0  = blockIdx.x * BN;

    const int arow = lane & 15;
    const int acol = (lane >> 4) << 3;
    const int brow = (lane & 7) + ((lane >> 4) << 3);
    const int bcol = ((lane >> 3) & 1) << 3;

    float c[4][4][4] = {};

    auto aBase = [&](int s) { return hsm + s * STG_H; };
    auto bBase = [&](int s) { return hsm + s * STG_H + ASTG_H; };

    auto loadA = [&](int s, int k0) {
        __half* base = aBase(s);
        #pragma unroll
        for (int i = 0; i < 4; i++) {
            int ch = tid + i * 256;
            int r = ch >> 3, cc = ch & 7;
            cp_async16(base + r * RP + cc * 8,
                       Ab + (size_t)(m0 + r) * K + k0 + cc * 8);
        }
    };
    auto loadB = [&](int s, int k0) {
        __half* base = bBase(s);
        #pragma unroll
        for (int i = 0; i < 4; i++) {
            int ch = tid + i * 256;
            int r = ch >> 3, cc = ch & 7;
            cp_async16(base + r * RP + cc * 8,
                       Bb + (size_t)(n0 + r) * K + k0 + cc * 8);
        }
    };

    const int T = K / BKH;

    loadA(0, 0);   loadB(0, 0);   cp_commit();
    loadA(1, BKH); loadB(1, BKH); cp_commit();

    for (int t = 0; t < T; t++) {
        cp_wait1();
        __syncthreads();
        int tn = t + 2;
        if (tn < T) { loadA(tn % NSTAGE, tn * BKH); loadB(tn % NSTAGE, tn * BKH); }
        cp_commit();

        const int p = t % NSTAGE;
        const uint32_t As0 = smem_u32(aBase(p));
        const uint32_t Bs0 = smem_u32(bBase(p));

        #pragma unroll
        for (int ks = 0; ks < 4; ks++) {
            const int kh = ks * 16;
            uint32_t a[4][4], b[4][2];
            #pragma unroll
            for (int mt = 0; mt < 4; mt++) {
                uint32_t addr = As0 + ((wm * 64 + mt * 16 + arow) * RP + kh + acol) * 2;
                ldsm_x4(a[mt][0], a[mt][1], a[mt][2], a[mt][3], addr);
            }
            #pragma unroll
            for (int np = 0; np < 2; np++) {
                uint32_t addr = Bs0 + ((wn * 32 + np * 16 + brow) * RP + kh + bcol) * 2;
                ldsm_x4(b[2*np][0], b[2*np][1], b[2*np+1][0], b[2*np+1][1], addr);
            }
            #pragma unroll
            for (int mt = 0; mt < 4; mt++)
                #pragma unroll
                for (int nt = 0; nt < 4; nt++)
                    mma_f16(c[mt][nt], a[mt][0], a[mt][1], a[mt][2], a[mt][3],
                            b[nt][0], b[nt][1]);
        }
    }

    // epilogue
    #pragma unroll
    for (int mt = 0; mt < 4; mt++) {
        #pragma unroll
        for (int nt = 0; nt < 4; nt++) {
            const int col = n0 + wn * 32 + nt * 8 + 2 * t4;
            float b0 = 0.f, b1 = 0.f;
            if (HASBIAS) { b0 = bias[col]; b1 = bias[col + 1]; }
            #pragma unroll
            for (int h = 0; h < 2; h++) {
                const int row = m0 + wm * 64 + mt * 16 + g + h * 8;
                float v0 = (c[mt][nt][2 * h + 0] + b0) * alpha;
                float v1 = (c[mt][nt][2 * h + 1] + b1) * alpha;
                if (RELU) { v0 = fmaxf(v0, 0.f); v1 = fmaxf(v1, 0.f); }
                if (EXPF) { v0 = __expf(v0);     v1 = __expf(v1); }
                if (VT) {
                    // transposed half store: [b][col][s]
                    __half* Cb = (__half*)Cvb;
                    const int bb2 = row >> 11;            // row / SS
                    const int s  = row & (SS - 1);
                    Cb[((size_t)bb2 * DM + col)     * SS + s] = __float2half_rn(v0);
                    Cb[((size_t)bb2 * DM + col + 1) * SS + s] = __float2half_rn(v1);
                } else if (OUTH) {
                    __half* Cb = (__half*)Cvb;
                    *(__half2*)&Cb[(size_t)row * N + col] = __floats2half2_rn(v0, v1);
                } else {
                    float* Cb = (float*)Cvb;
                    *(float2*)&Cb[(size_t)row * N + col] = make_float2(v0, v1);
                }
            }
        }
    }
}

// generic batched-by-stride GEMM
template<int HASBIAS, int RELU, int OUTH, int EXPF>
__global__ void __launch_bounds__(256, 2)
gemm_h(const __half* __restrict__ A, const __half* __restrict__ Bt,
       const float* __restrict__ bias, void* __restrict__ Cv,
       int N, int K, size_t sA, size_t sB, size_t sC, float alpha)
{
    const __half* Ab = A  + (size_t)blockIdx.z * sA;
    const __half* Bb = Bt + (size_t)blockIdx.z * sB;
    void* Cb = OUTH ? (void*)((__half*)Cv + (size_t)blockIdx.z * sC)
                    : (void*)((float*)Cv + (size_t)blockIdx.z * sC);
    gemm_core<HASBIAS, RELU, OUTH, EXPF, 0>(Ab, Bb, bias, Cb, N, K, alpha);
}

// fused QKV: one launch, blockIdx.z selects q/k/v; V (z==2) is written transposed.
__global__ void __launch_bounds__(256, 2)
gemm_qkv(const __half* __restrict__ qa, const __half* __restrict__ ka,
         const __half* __restrict__ va,
         const __half* __restrict__ wq, const __half* __restrict__ wk,
         const __half* __restrict__ wv,
         const float* __restrict__ bq, const float* __restrict__ bk,
         const float* __restrict__ bv,
         __half* __restrict__ oq, __half* __restrict__ ok,
         __half* __restrict__ ovt, float alphaQ)
{
    const int z = blockIdx.z;
    if (z == 2) {
        gemm_core<1, 0, 1, 0, 1>(va, wv, bv, ovt, DM, DM, 1.f);
    } else {
        const __half* Ab = (z == 0) ? qa : ka;
        const __half* Bb = (z == 0) ? wq : wk;
        const float*  bb = (z == 0) ? bq : bk;
        __half*       Cb = (z == 0) ? oq : ok;
        const float   al = (z == 0) ? alphaQ : 1.f;
        gemm_core<1, 0, 1, 0, 0>(Ab, Bb, bb, Cb, DM, DM, al);
    }
}

// fused P@V + rowsum: grid (DM/BN, SS/BM + 1, BB) = (4, 17, 4) = 272 CTAs <= 296 slots.
// blockIdx.y < SS/BM : GEMM CTA (attn_unnorm = P @ V)
// blockIdx.y == SS/BM: rowsum CTA — 16 such CTAs, each sums 512 rows of P
__global__ void __launch_bounds__(256, 2)
gemm_pv_rowsum(const __half* __restrict__ P, const __half* __restrict__ VT,
               float* __restrict__ attn, float* __restrict__ rinv)
{
    if (blockIdx.y == SS / BM) {
        const int warp = threadIdx.x >> 5, lane = threadIdx.x & 31;
        const int chunk = blockIdx.z * 4 + blockIdx.x;           // 0..15
        #pragma unroll 1
        for (int i = 0; i < 64; i++) {
            const size_t row = (size_t)chunk * 512 + warp * 64 + i;
            const uint4* p = (const uint4*)(P + row * SS);       // 256 uint4
            float s = 0.f;
            #pragma unroll
            for (int j = 0; j < 8; j++) {
                uint4 u = p[lane + j * 32];
                const __half2* h = (const __half2*)&u;
                #pragma unroll
                for (int t = 0; t < 4; t++) {
                    float2 f = __half22float2(h[t]);
                    s += f.x + f.y;
                }
            }
            #pragma unroll
            for (int o = 16; o; o >>= 1) s += __shfl_xor_sync(0xffffffffu, s, o);
            if (lane == 0) rinv[row] = 1.f / s;
        }
        return;
    }
    const __half* Ab = P  + (size_t)blockIdx.z * SS * SS;
    const __half* Bb = VT + (size_t)blockIdx.z * DM * SS;
    float*        Cb = attn + (size_t)blockIdx.z * SS * DM;
    gemm_core<0, 0, 0, 0, 0>(Ab, Bb, nullptr, Cb, DM, SS, 1.f);
}

// ---------------- ONE prep launch: f2h of q/k/v + all 5 weight transposes ----------------
__global__ void prep_kernel(
    const float* __restrict__ q, const float* __restrict__ k, const float* __restrict__ v,
    __half* __restrict__ oq, __half* __restrict__ ok, __half* __restrict__ ov,
    const float* __restrict__ Wq, const float* __restrict__ Wk, const float* __restrict__ Wv,
    __half* __restrict__ oWq, __half* __restrict__ oWk, __half* __restrict__ oWv,
    const float* __restrict__ W1, __half* __restrict__ oW1,
    const float* __restrict__ W2, __half* __restrict__ oW2)
{
    const int b = blockIdx.x;

    if (b < PREP_R0) {
        const int t  = b / PREP_F2H;
        const int bx = b % PREP_F2H;
        const float* in  = (t == 0) ? q  : (t == 1) ? k  : v;
        __half*      out = (t == 0) ? oq : (t == 1) ? ok : ov;
        const int i = (bx * 256 + threadIdx.x) * 4;
        float4 val = *(const float4*)(in + i);
        *(__half2*)(out + i)     = __floats2half2_rn(val.x, val.y);
        *(__half2*)(out + i + 2) = __floats2half2_rn(val.z, val.w);
        return;
    }

    __shared__ float tile[32][33];
    const int tx = threadIdx.x & 31, ty = threadIdx.x >> 5;
    const float* in; __half* out; int R, C, r0, c0;

    if (b < PREP_R1) {
        const int local = b - PREP_R0;
        const int z = local / 256, rem = local % 256;
        in  = (z == 0) ? Wq  : (z == 1) ? Wk  : Wv;
        out = (z == 0) ? oWq : (z == 1) ? oWk : oWv;
        R = DM; C = DM;
        r0 = (rem & 15) * 32;
        c0 = (rem >> 4) * 32;
    } else if (b < PREP_R2) {
        const int local = b - PREP_R1;
        in = W1; out = oW1; R = DM; C = DF;
        r0 = (local & 15) * 32;
        c0 = (local >> 4) * 32;
    } else {
        const int local = b - PREP_R2;
        in = W2; out = oW2; R = DF; C = DM;
        r0 = (local & 63) * 32;
        c0 = (local >> 6) * 32;
    }

    #pragma unroll
    for (int i = 0; i < 4; i++)
        tile[ty + i * 8][tx] = in[(size_t)(r0 + ty + i * 8) * C + c0 + tx];
    __syncthreads();
    #pragma unroll
    for (int i = 0; i < 4; i++)
        out[(size_t)(c0 + ty + i * 8) * R + r0 + tx] = __float2half_rn(tile[tx][ty + i * 8]);
}

// ---------------- warp-per-row residual add + LayerNorm (no block barriers) ----------------
// one warp = one row of 512 floats; 16 elems/lane; fused sum+sumsq shuffle reduction.
template<int WRITEH, int SCALEA>
__global__ void add_ln_warp(const float* __restrict__ a, const float* __restrict__ b,
                            const float* __restrict__ gamma, const float* __restrict__ beta,
                            const float* __restrict__ ascale,
                            float* __restrict__ out, __half* __restrict__ outh)
{
    const int warp = threadIdx.x >> 5, lane = threadIdx.x & 31;
    const size_t row = (size_t)blockIdx.x * 8 + warp;
    const float4* ar = (const float4*)(a + row * DM);
    const float4* br = (const float4*)(b + row * DM);

    const float sc = SCALEA ? ascale[row] : 1.f;

    float4 v[4];
    float s = 0.f, sq = 0.f;
    #pragma unroll
    for (int i = 0; i < 4; i++) {
        float4 av = ar[lane + 32 * i];
        float4 bv = br[lane + 32 * i];
        v[i].x = av.x * sc + bv.x;
        v[i].y = av.y * sc + bv.y;
        v[i].z = av.z * sc + bv.z;
        v[i].w = av.w * sc + bv.w;
        s  += v[i].x + v[i].y + v[i].z + v[i].w;
        sq += v[i].x*v[i].x + v[i].y*v[i].y + v[i].z*v[i].z + v[i].w*v[i].w;
    }
    #pragma unroll
    for (int o = 16; o; o >>= 1) {
        s  += __shfl_xor_sync(0xffffffffu, s,  o);
        sq += __shfl_xor_sync(0xffffffffu, sq, o);
    }

    const float mean = s * (1.f / DM);
    const float var  = sq * (1.f / DM) - mean * mean;
    const float inv  = rsqrtf(var + 1e-5f);

    float4* o4 = (float4*)(out + row * DM);
    #pragma unroll
    for (int i = 0; i < 4; i++) {
        const int idx = lane + 32 * i;
        float4 gv = ((const float4*)gamma)[idx];
        float4 be = ((const float4*)beta)[idx];
        float4 o;
        o.x = (v[i].x - mean) * inv * gv.x + be.x;
        o.y = (v[i].y - mean) * inv * gv.y + be.y;
        o.z = (v[i].z - mean) * inv * gv.z + be.z;
        o.w = (v[i].w - mean) * inv * gv.w + be.w;
        o4[idx] = o;
        if (WRITEH) {
            __half2* oh = (__half2*)(outh + row * DM) + idx * 2;
            oh[0] = __floats2half2_rn(o.x, o.y);
            oh[1] = __floats2half2_rn(o.z, o.w);
        }
    }
}

// ---------------- launch ----------------
extern "C" void kernel_launch(void* const* d_in, const int* in_sizes, int n_in,
                              void* d_out, int out_size)
{
    const float* q  = (const float*)d_in[0];
    const float* k  = (const float*)d_in[1];
    const float* v  = (const float*)d_in[2];
    const float* x  = (const float*)d_in[3];
    const float* Wq = (const float*)d_in[4];
    const float* bq = (const float*)d_in[5];
    const float* Wk = (const float*)d_in[6];
    const float* bk = (const float*)d_in[7];
    const float* Wv = (const float*)d_in[8];
    const float* bv = (const float*)d_in[9];
    const float* g1 = (const float*)d_in[10];
    const float* be1= (const float*)d_in[11];
    const float* W1 = (const float*)d_in[12];
    const float* b1 = (const float*)d_in[13];
    const float* W2 = (const float*)d_in[14];
    const float* b2 = (const float*)d_in[15];
    const float* g2 = (const float*)d_in[16];
    const float* be2= (const float*)d_in[17];
    float* out = (float*)d_out;

    __half *pqh, *pkh, *pvh, *pQh, *pKh, *pVTh, *pPh, *phh, *pf;
    __half *pWqT, *pWkT, *pWvT, *pW1T, *pW2T;
    float *pRinv, *pAttn, *pH, *pF2;
    cudaGetSymbolAddress((void**)&pqh,  g_qh);
    cudaGetSymbolAddress((void**)&pkh,  g_kh);
    cudaGetSymbolAddress((void**)&pvh,  g_vh);
    cudaGetSymbolAddress((void**)&pQh,  g_Qh);
    cudaGetSymbolAddress((void**)&pKh,  g_Kh);
    cudaGetSymbolAddress((void**)&pVTh, g_VTh);
    cudaGetSymbolAddress((void**)&pPh,  g_Ph);
    cudaGetSymbolAddress((void**)&pRinv,g_rinv);
    cudaGetSymbolAddress((void**)&pAttn,g_attn);
    cudaGetSymbolAddress((void**)&pH,   g_h);
    cudaGetSymbolAddress((void**)&phh,  g_hh);
    cudaGetSymbolAddress((void**)&pf,   g_f);
    cudaGetSymbolAddress((void**)&pF2,  g_f2);
    cudaGetSymbolAddress((void**)&pWqT, g_WqT);
    cudaGetSymbolAddress((void**)&pWkT, g_WkT);
    cudaGetSymbolAddress((void**)&pWvT, g_WvT);
    cudaGetSymbolAddress((void**)&pW1T, g_W1T);
    cudaGetSymbolAddress((void**)&pW2T, g_W2T);

    cudaFuncSetAttribute((const void*)gemm_qkv,        cudaFuncAttributeMaxDynamicSharedMemorySize, SMEM_H);
    cudaFuncSetAttribute((const void*)gemm_pv_rowsum,  cudaFuncAttributeMaxDynamicSharedMemorySize, SMEM_H);
    cudaFuncSetAttribute((const void*)gemm_h<0,0,1,1>, cudaFuncAttributeMaxDynamicSharedMemorySize, SMEM_H);
    cudaFuncSetAttribute((const void*)gemm_h<1,1,1,0>, cudaFuncAttributeMaxDynamicSharedMemorySize, SMEM_H);
    cudaFuncSetAttribute((const void*)gemm_h<1,0,0,0>, cudaFuncAttributeMaxDynamicSharedMemorySize, SMEM_H);

    const float inv_sqrt_d = 1.f / sqrtf((float)DM);

    // 0) ALL prep in one launch: q/k/v fp32->fp16 + 5 weight transposes
    prep_kernel<<<PREP_TOT, 256>>>(q, k, v, pqh, pkh, pvh,
                                   Wq, Wk, Wv, pWqT, pWkT, pWvT,
                                   W1, pW1T, W2, pW2T);

    // 1) QKV projections, single fused launch; V written directly transposed
    {
        dim3 grid(DM / BN, ROWS / BM, 3);
        gemm_qkv<<<grid, 256, SMEM_H>>>(pqh, pkh, pvh, pWqT, pWkT, pWvT,
                                        bq, bk, bv, pQh, pKh, pVTh, inv_sqrt_d);
    }

    // 2) P = exp(Qs @ K^T) -> half, fused epilogue (no max-sub: |scores| <~ 6)
    {
        dim3 grid(SS / BN, SS / BM, BB);
        gemm_h<0,0,1,1><<<grid, 256, SMEM_H>>>(pQh, pKh, nullptr, pPh, SS, DM,
                                               (size_t)SS*DM, (size_t)SS*DM, (size_t)SS*SS, 1.f);
    }

    // 3) attn_unnorm = P @ V and per-row 1/sum(P), ONE launch, 272 CTAs (single wave)
    {
        dim3 grid(DM / BN, SS / BM + 1, BB);
        gemm_pv_rowsum<<<grid, 256, SMEM_H>>>(pPh, pVTh, pAttn, pRinv);
    }

    // 4) h = LN(attn_unnorm * rinv + x), warp-per-row, fp32 + half copy
    add_ln_warp<1,1><<<ROWS / 8, 256>>>(pAttn, x, g1, be1, pRinv, pH, phh);

    // 5) f = relu(h @ W1 + b1) -> half
    {
        dim3 grid(DF / BN, ROWS / BM, 1);
        gemm_h<1,1,1,0><<<grid, 256, SMEM_H>>>(phh, pW1T, b1, pf, DF, DM, 0, 0, 0, 1.f);
    }

    // 6) f2 = f @ W2 + b2 -> fp32
    {
        dim3 grid(DM / BN, ROWS / BM, 1);
        gemm_h<1,0,0,0><<<grid, 256, SMEM_H>>>(pf, pW2T, b2, pF2, DM, DF, 0, 0, 0, 1.f);
    }

    // 7) out = LN(f2 + h), warp-per-row
    add_ln_warp<0,0><<<ROWS / 8, 256>>>(pF2, pH, g2, be2, nullptr, out, nullptr);
}